// round 13
// baseline (speedup 1.0000x reference)
#include <cuda_runtime.h>
#include <cuda_bf16.h>
#include <cuda_fp16.h>
#include <cstdint>

// N=50000 nodes, E=800000 edges, IN_DIM=256, HEADS=4, HID=64 -> out 256.
#define MAXN 50000
#define MAXE 800000
#define MAXT (MAXE + MAXN)
#define DIM 256
#define NEG_SLOPE 0.2f

// ------------------------- device scratch -------------------------
__device__ __align__(16) __half g_hh[(size_t)MAXN * DIM];  // projected features fp16
__device__ __nv_bfloat16  g_xhi[(size_t)MAXN * DIM];   // x split hi
__device__ __nv_bfloat16  g_xlo[(size_t)MAXN * DIM];   // x split lo
__device__ __nv_bfloat16  g_wthi[DIM * DIM];           // W^T split hi: [n][k]
__device__ __nv_bfloat16  g_wtlo[DIM * DIM];
__device__ float4 g_asrc[MAXN];
__device__ float4 g_adst[MAXN];
__device__ int    g_deg[MAXN];
__device__ int    g_rowoff[MAXN];
__device__ int    g_cursor[MAXN];
__device__ int    g_slot_src[MAXT];    // src node, binned by dst
__device__ __align__(16) float4 g_slot_w[MAXT];  // exp(e) per edge, binned by dst
__device__ int    g_bsum[64];
__device__ int    g_bbase[64];
__device__ int    g_idx_stride;        // 1 = int32 indices, 2 = int64 low word

// ------------------------- helpers -------------------------
__device__ __forceinline__ uint32_t smem_u32(const void* p) {
    uint32_t a;
    asm("{ .reg .u64 t; cvta.to.shared.u64 t, %1; cvt.u32.u64 %0, t; }"
        : "=r"(a) : "l"(p));
    return a;
}

// ------------------------- 0) dtype detection -------------------------
// JAX default x64-off silently makes edge_index int32; detect via odd words.
__global__ void detect_idx_kernel(const int* __restrict__ ei32, int E)
{
    __shared__ int s_nonzero;
    if (threadIdx.x == 0) s_nonzero = 0;
    __syncthreads();
    int nz = 0;
    int samples = (E < 4096) ? E : 4096;
    for (int i = threadIdx.x; i < samples; i += blockDim.x)
        nz |= ei32[2 * i + 1];
    if (nz) atomicOr(&s_nonzero, 1);
    __syncthreads();
    if (threadIdx.x == 0) g_idx_stride = s_nonzero ? 1 : 2;
}

__device__ __forceinline__ void load_edge(const int* __restrict__ ei32,
                                          int t, int E, int stride, int& s, int& d)
{
    s = ei32[(size_t)t * stride];
    d = ei32[((size_t)E + t) * stride];
}

// ------------------------- 1a) W transpose + bf16 split -------------------------
__global__ void prep_w_kernel(const float* __restrict__ W)
{
    int i = blockIdx.x * blockDim.x + threadIdx.x;   // i = k*256 + n
    if (i < DIM * DIM) {
        int k = i >> 8, n = i & 255;
        float w = W[i];
        __nv_bfloat16 hi = __float2bfloat16(w);
        __nv_bfloat16 lo = __float2bfloat16(w - __bfloat162float(hi));
        g_wthi[n * DIM + k] = hi;
        g_wtlo[n * DIM + k] = lo;
    }
}

// ------------------------- 1b) x bf16 split (+ deg zero fused) ----------
__global__ void split_x_kernel(const float* __restrict__ x, int total4, int N)
{
    int i = blockIdx.x * blockDim.x + threadIdx.x;
    if (i < total4) {
        float4 v = ((const float4*)x)[i];
        __nv_bfloat16 h0 = __float2bfloat16(v.x), h1 = __float2bfloat16(v.y);
        __nv_bfloat16 h2 = __float2bfloat16(v.z), h3 = __float2bfloat16(v.w);
        __nv_bfloat16 l0 = __float2bfloat16(v.x - __bfloat162float(h0));
        __nv_bfloat16 l1 = __float2bfloat16(v.y - __bfloat162float(h1));
        __nv_bfloat16 l2 = __float2bfloat16(v.z - __bfloat162float(h2));
        __nv_bfloat16 l3 = __float2bfloat16(v.w - __bfloat162float(h3));
        ((__nv_bfloat162*)g_xhi)[2 * i]     = __halves2bfloat162(h0, h1);
        ((__nv_bfloat162*)g_xhi)[2 * i + 1] = __halves2bfloat162(h2, h3);
        ((__nv_bfloat162*)g_xlo)[2 * i]     = __halves2bfloat162(l0, l1);
        ((__nv_bfloat162*)g_xlo)[2 * i + 1] = __halves2bfloat162(l2, l3);
    }
    if (i < N) g_deg[i] = 0;
}

// ------------------------- 2) GEMM via mma.sync bf16x3 + fused logits ---------
// h = x@W with split: hi*hi + lo*hi + hi*lo, fp32 accumulate.
// (tcgen05 is compile-blocked: harness lowers via compute_103 PTX, no 'a' feat.)
// CTA tile 128(M) x 256(N), BK=64, **512 threads** (4x4 warps), warp tile 32x64.
// 16 warps/SM (= R11 occupancy) with B staging amortized over 2x output rows.
// Epilogue: fp16 h store + per-row att_src/att_dst dots (head == warp_n).
#define GBM 128
#define GBK 64
#define GTHREADS 512
#define ASTR 72   // bf16 stride with +8 pad -> ldmatrix conflict-free
#define SM_AS 0
#define SM_BS (GBM * ASTR * 2)                    // 18432
#define SM_ATTS (SM_BS + DIM * ASTR * 2)          // 18432+36864 = 55296
#define SM_ATTD (SM_ATTS + DIM * 4)
#define SMEM_GEMM (SM_ATTD + DIM * 4)             // 57344

__global__ __launch_bounds__(GTHREADS, 1)
void gemm_mma_kernel(const float* __restrict__ att_src,
                     const float* __restrict__ att_dst, int M)
{
    extern __shared__ __align__(16) char dyn[];
    __nv_bfloat16* As = (__nv_bfloat16*)(dyn + SM_AS);   // 128 x 72
    __nv_bfloat16* Bs = (__nv_bfloat16*)(dyn + SM_BS);   // 256 x 72
    float* satts = (float*)(dyn + SM_ATTS);
    float* sattd = (float*)(dyn + SM_ATTD);

    int tid = threadIdx.x, lane = tid & 31, wid = tid >> 5;
    int warp_m = wid & 3;        // 0..3 (32 rows each)
    int warp_n = wid >> 2;       // 0..3 (== head index, 64 cols)
    int brow = blockIdx.x * GBM;

    if (tid < DIM) {
        satts[tid] = att_src[tid];
        sattd[tid] = att_dst[tid];
    }

    float acc[2][8][4];
    #pragma unroll
    for (int mi = 0; mi < 2; mi++)
        #pragma unroll
        for (int ni = 0; ni < 8; ni++)
            #pragma unroll
            for (int q = 0; q < 4; q++) acc[mi][ni][q] = 0.f;

    uint32_t As_a = smem_u32(As);
    uint32_t Bs_a = smem_u32(Bs);

    // ldmatrix lane address components
    int a_row = warp_m * 32 + (lane & 15);              // + mi*16
    int a_k   = (lane >> 4) << 3;                       // 0/8, + ks*16
    // B x4: {n+0,k0},{n+0,k8},{n+8,k0},{n+8,k8}
    int b_row = warp_n * 64 + ((lane >> 4) & 1) * 8 + (lane & 7);  // + np*16
    int b_k   = ((lane >> 3) & 1) << 3;                 // + ks*16

    for (int it = 0; it < 12; it++) {
        int pass = it >> 2, kc = it & 3;
        const __nv_bfloat16* ap = (pass == 1) ? g_xlo  : g_xhi;
        const __nv_bfloat16* bp = (pass == 2) ? g_wtlo : g_wthi;

        __syncthreads();   // previous iter's reads done
        // A: 128 rows x 64 bf16 = 1024 uint4, 2 per thread
        #pragma unroll
        for (int i = 0; i < 2; i++) {
            int idx = tid + i * GTHREADS;
            int r = idx >> 3, c = (idx & 7) << 3;
            uint4 v = make_uint4(0u, 0u, 0u, 0u);
            if (brow + r < M)
                v = *(const uint4*)(ap + (size_t)(brow + r) * DIM + kc * GBK + c);
            *(uint4*)&As[r * ASTR + c] = v;
        }
        // B: 256 rows x 64 bf16 = 2048 uint4, 4 per thread
        #pragma unroll
        for (int i = 0; i < 4; i++) {
            int idx = tid + i * GTHREADS;
            int r = idx >> 3, c = (idx & 7) << 3;
            uint4 v = *(const uint4*)(bp + (size_t)r * DIM + kc * GBK + c);
            *(uint4*)&Bs[r * ASTR + c] = v;
        }
        __syncthreads();

        #pragma unroll
        for (int ks = 0; ks < 4; ks++) {
            uint32_t a_frag[2][4];
            #pragma unroll
            for (int mi = 0; mi < 2; mi++) {
                uint32_t addr = As_a +
                    (uint32_t)(((a_row + mi * 16) * ASTR + ks * 16 + a_k) * 2);
                asm volatile(
                    "ldmatrix.sync.aligned.m8n8.x4.shared.b16 {%0,%1,%2,%3}, [%4];"
                    : "=r"(a_frag[mi][0]), "=r"(a_frag[mi][1]),
                      "=r"(a_frag[mi][2]), "=r"(a_frag[mi][3])
                    : "r"(addr));
            }
            #pragma unroll
            for (int np = 0; np < 4; np++) {   // ni pairs {2np, 2np+1}
                uint32_t b0, b1, b2, b3;
                uint32_t addr = Bs_a +
                    (uint32_t)(((b_row + np * 16) * ASTR + ks * 16 + b_k) * 2);
                asm volatile(
                    "ldmatrix.sync.aligned.m8n8.x4.shared.b16 {%0,%1,%2,%3}, [%4];"
                    : "=r"(b0), "=r"(b1), "=r"(b2), "=r"(b3) : "r"(addr));
                #pragma unroll
                for (int mi = 0; mi < 2; mi++) {
                    asm volatile(
                        "mma.sync.aligned.m16n8k16.row.col.f32.bf16.bf16.f32 "
                        "{%0,%1,%2,%3}, {%4,%5,%6,%7}, {%8,%9}, {%0,%1,%2,%3};"
                        : "+f"(acc[mi][2*np][0]), "+f"(acc[mi][2*np][1]),
                          "+f"(acc[mi][2*np][2]), "+f"(acc[mi][2*np][3])
                        : "r"(a_frag[mi][0]), "r"(a_frag[mi][1]),
                          "r"(a_frag[mi][2]), "r"(a_frag[mi][3]),
                          "r"(b0), "r"(b1));
                    asm volatile(
                        "mma.sync.aligned.m16n8k16.row.col.f32.bf16.bf16.f32 "
                        "{%0,%1,%2,%3}, {%4,%5,%6,%7}, {%8,%9}, {%0,%1,%2,%3};"
                        : "+f"(acc[mi][2*np+1][0]), "+f"(acc[mi][2*np+1][1]),
                          "+f"(acc[mi][2*np+1][2]), "+f"(acc[mi][2*np+1][3])
                        : "r"(a_frag[mi][0]), "r"(a_frag[mi][1]),
                          "r"(a_frag[mi][2]), "r"(a_frag[mi][3]),
                          "r"(b2), "r"(b3));
                }
            }
        }
    }

    // Epilogue: fp16 h store + fused per-head attention dots.
    #pragma unroll
    for (int mi = 0; mi < 2; mi++) {
        int r_lo = brow + warp_m * 32 + mi * 16 + (lane >> 2);
        int r_hi = r_lo + 8;
        float s_lo = 0.f, d_lo = 0.f, s_hi = 0.f, d_hi = 0.f;
        #pragma unroll
        for (int ni = 0; ni < 8; ni++) {
            int c0 = warp_n * 64 + ni * 8 + (lane & 3) * 2;
            float v0 = acc[mi][ni][0], v1 = acc[mi][ni][1];
            float v2 = acc[mi][ni][2], v3 = acc[mi][ni][3];
            if (r_lo < M)
                *(__half2*)(g_hh + (size_t)r_lo * DIM + c0) =
                    __float22half2_rn(make_float2(v0, v1));
            if (r_hi < M)
                *(__half2*)(g_hh + (size_t)r_hi * DIM + c0) =
                    __float22half2_rn(make_float2(v2, v3));
            float ts0 = satts[c0], ts1 = satts[c0 + 1];
            float td0 = sattd[c0], td1 = sattd[c0 + 1];
            s_lo += v0 * ts0 + v1 * ts1;
            d_lo += v0 * td0 + v1 * td1;
            s_hi += v2 * ts0 + v3 * ts1;
            d_hi += v2 * td0 + v3 * td1;
        }
        #pragma unroll
        for (int off = 1; off <= 2; off <<= 1) {
            s_lo += __shfl_xor_sync(0xffffffffu, s_lo, off);
            d_lo += __shfl_xor_sync(0xffffffffu, d_lo, off);
            s_hi += __shfl_xor_sync(0xffffffffu, s_hi, off);
            d_hi += __shfl_xor_sync(0xffffffffu, d_hi, off);
        }
        if ((lane & 3) == 0) {
            if (r_lo < M) {
                ((float*)&g_asrc[r_lo])[warp_n] = s_lo;
                ((float*)&g_adst[r_lo])[warp_n] = d_lo;
            }
            if (r_hi < M) {
                ((float*)&g_asrc[r_hi])[warp_n] = s_hi;
                ((float*)&g_adst[r_hi])[warp_n] = d_hi;
            }
        }
    }
}

// ------------------------- 3) degree count -------------------------
__global__ __launch_bounds__(256)
void deg_count_kernel(const int* __restrict__ ei32, int E, int T)
{
    int t = blockIdx.x * blockDim.x + threadIdx.x;
    if (t >= T) return;
    int d;
    if (t < E) d = ei32[((size_t)E + t) * g_idx_stride];
    else       d = t - E;
    atomicAdd(&g_deg[d], 1);
}

// ------------------------- 4) CSR scan -------------------------
__global__ void scan1_kernel(int N)
{
    __shared__ int sh[1024];
    int i = blockIdx.x * 1024 + threadIdx.x;
    int v = (i < N) ? g_deg[i] : 0;
    sh[threadIdx.x] = v;
    __syncthreads();
    #pragma unroll
    for (int off = 1; off < 1024; off <<= 1) {
        int t = (threadIdx.x >= off) ? sh[threadIdx.x - off] : 0;
        __syncthreads();
        sh[threadIdx.x] += t;
        __syncthreads();
    }
    if (i < N) g_rowoff[i] = sh[threadIdx.x] - v;   // exclusive within block
    if (threadIdx.x == 1023) g_bsum[blockIdx.x] = sh[1023];
}

__global__ void scan2_kernel(int nb)
{
    if (threadIdx.x == 0) {
        int run = 0;
        for (int b = 0; b < nb; b++) { g_bbase[b] = run; run += g_bsum[b]; }
    }
}

__global__ void scan3_kernel(int N)
{
    int i = blockIdx.x * blockDim.x + threadIdx.x;
    if (i < N) {
        int o = g_rowoff[i] + g_bbase[i >> 10];
        g_rowoff[i] = o;
        g_cursor[i] = o;
    }
}

// ------------------------- 5) edge logits + slot fill -------------------------
// num = exp(leaky_relu(a_src[s] + a_dst[d])), written in dst-binned slot order.
// No denominator pass: aggregate sums num itself (divide once at the end).
__global__ __launch_bounds__(256)
void logits_fill_kernel(const int* __restrict__ ei32, int E, int T)
{
    int t = blockIdx.x * blockDim.x + threadIdx.x;
    if (t >= T) return;
    int stride = g_idx_stride;
    int s, d;
    if (t < E) load_edge(ei32, t, E, stride, s, d);
    else       s = d = t - E;

    float4 a = g_asrc[s];
    float4 b = g_adst[d];
    float4 e = make_float4(a.x + b.x, a.y + b.y, a.z + b.z, a.w + b.w);
    e.x = e.x > 0.f ? e.x : NEG_SLOPE * e.x;
    e.y = e.y > 0.f ? e.y : NEG_SLOPE * e.y;
    e.z = e.z > 0.f ? e.z : NEG_SLOPE * e.z;
    e.w = e.w > 0.f ? e.w : NEG_SLOPE * e.w;
    // max-shift unnecessary: |e| small, exp fp32-safe, shift cancels in num/denom
    float4 nm = make_float4(expf(e.x), expf(e.y), expf(e.z), expf(e.w));

    int pos = atomicAdd(&g_cursor[d], 1);
    g_slot_src[pos] = s;
    g_slot_w[pos]   = nm;
}

// ------------------------- 6) aggregate (warp/node) + bias + ReLU -------------
// Lane covers halves [8*lane, 8*lane+8) of the 256-wide row -> head = lane>>3.
// denom accumulated in-loop; single divide at the end.
__global__ __launch_bounds__(256)
void aggregate_kernel(float* __restrict__ out, const float* __restrict__ bias, int N)
{
    int g    = blockIdx.x * blockDim.x + threadIdx.x;
    int node = g >> 5;
    int lane = threadIdx.x & 31;
    if (node >= N) return;

    int off = g_rowoff[node];
    int deg = g_deg[node];
    int head = lane >> 3;

    float a0 = 0.f, a1 = 0.f, a2 = 0.f, a3 = 0.f;
    float a4 = 0.f, a5 = 0.f, a6 = 0.f, a7 = 0.f;
    float dsum = 0.f;

    const uint4* hbase = (const uint4*)g_hh;   // 32 uint4 (512B) per row
    for (int e = 0; e < deg; e++) {
        int  sidx = g_slot_src[off + e];
        float4 nm = g_slot_w[off + e];
        float w = (head == 0) ? nm.x : (head == 1) ? nm.y : (head == 2) ? nm.z : nm.w;
        dsum += w;
        uint4 v = hbase[(size_t)sidx * 32 + lane];   // 8 halves
        float2 f0 = __half22float2(*(__half2*)&v.x);
        float2 f1 = __half22float2(*(__half2*)&v.y);
        float2 f2 = __half22float2(*(__half2*)&v.z);
        float2 f3 = __half22float2(*(__half2*)&v.w);
        a0 = fmaf(w, f0.x, a0); a1 = fmaf(w, f0.y, a1);
        a2 = fmaf(w, f1.x, a2); a3 = fmaf(w, f1.y, a3);
        a4 = fmaf(w, f2.x, a4); a5 = fmaf(w, f2.y, a5);
        a6 = fmaf(w, f3.x, a6); a7 = fmaf(w, f3.y, a7);
    }

    float inv = 1.f / dsum;   // self loops guarantee deg >= 1, dsum > 0
    const float4* b4 = (const float4*)bias;
    float4 bb0 = b4[2 * lane], bb1 = b4[2 * lane + 1];
    float4 o0 = make_float4(fmaxf(fmaf(a0, inv, bb0.x), 0.f),
                            fmaxf(fmaf(a1, inv, bb0.y), 0.f),
                            fmaxf(fmaf(a2, inv, bb0.z), 0.f),
                            fmaxf(fmaf(a3, inv, bb0.w), 0.f));
    float4 o1 = make_float4(fmaxf(fmaf(a4, inv, bb1.x), 0.f),
                            fmaxf(fmaf(a5, inv, bb1.y), 0.f),
                            fmaxf(fmaf(a6, inv, bb1.z), 0.f),
                            fmaxf(fmaf(a7, inv, bb1.w), 0.f));

    float4* orow = (float4*)(out + (size_t)node * DIM);
    orow[2 * lane]     = o0;
    orow[2 * lane + 1] = o1;
}

// ------------------------- launch -------------------------
extern "C" void kernel_launch(void* const* d_in, const int* in_sizes, int n_in,
                              void* d_out, int out_size)
{
    const float* x       = (const float*)d_in[0];
    const int*   ei32    = (const int*)d_in[1];
    const float* W       = (const float*)d_in[2];
    const float* att_src = (const float*)d_in[3];
    const float* att_dst = (const float*)d_in[4];
    const float* bias    = (const float*)d_in[5];

    int N = in_sizes[0] / DIM;   // 50000
    int E = in_sizes[1] / 2;     // 800000
    int T = E + N;
    float* out = (float*)d_out;

    static int s_attr_done = 0;
    if (!s_attr_done) {
        cudaFuncSetAttribute(gemm_mma_kernel,
                             cudaFuncAttributeMaxDynamicSharedMemorySize, SMEM_GEMM);
        s_attr_done = 1;
    }

    // 0) edge index dtype
    detect_idx_kernel<<<1, 256>>>(ei32, E);

    // 1) bf16 splits of W^T and x (+ deg zero)
    prep_w_kernel<<<(DIM * DIM + 255) / 256, 256>>>(W);
    split_x_kernel<<<(N * DIM / 4 + 255) / 256, 256>>>(x, N * DIM / 4, N);

    // 2) degree count + CSR scan (independent of GEMM)
    deg_count_kernel<<<(T + 255) / 256, 256>>>(ei32, E, T);
    int nb = (N + 1023) / 1024;
    scan1_kernel<<<nb, 1024>>>(N);
    scan2_kernel<<<1, 32>>>(nb);
    scan3_kernel<<<(N + 255) / 256, 256>>>(N);

    // 3) tensor-core GEMM (mma.sync bf16x3, 512 thr, 128x256 tile) + fused logits
    gemm_mma_kernel<<<(N + GBM - 1) / GBM, GTHREADS, SMEM_GEMM>>>(att_src, att_dst, N);

    // 4) edge softmax numerators, dst-binned
    logits_fill_kernel<<<(T + 255) / 256, 256>>>(ei32, E, T);

    // 5) per-node aggregation + bias + ReLU (denom summed in-loop)
    aggregate_kernel<<<(N * 32 + 255) / 256, 256>>>(out, bias, N);
}

// round 15
// speedup vs baseline: 1.0802x; 1.0802x over previous
#include <cuda_runtime.h>
#include <cuda_bf16.h>
#include <cuda_fp16.h>
#include <cstdint>

// N=50000 nodes, E=800000 edges, IN_DIM=256, HEADS=4, HID=64 -> out 256.
#define MAXN 50000
#define MAXE 800000
#define MAXT (MAXE + MAXN)
#define DIM 256
#define NEG_SLOPE 0.2f

// ------------------------- device scratch -------------------------
__device__ __align__(16) __half g_hh[(size_t)MAXN * DIM];  // projected features fp16
__device__ __nv_bfloat16  g_xhi[(size_t)MAXN * DIM];   // x split hi
__device__ __nv_bfloat16  g_xlo[(size_t)MAXN * DIM];   // x split lo
__device__ __nv_bfloat16  g_wthi[DIM * DIM];           // W^T split hi: [n][k]
__device__ __nv_bfloat16  g_wtlo[DIM * DIM];
__device__ float4 g_asrc[MAXN];
__device__ float4 g_adst[MAXN];
__device__ float4 g_num[MAXT];         // exp(e) per edge
__device__ int    g_deg[MAXN];
__device__ int    g_rowoff[MAXN];
__device__ int    g_cursor[MAXN];
__device__ int2   g_slot[MAXT];        // {src, edge_id} binned by dst
__device__ int    g_bsum[64];
__device__ int    g_bbase[64];
__device__ int    g_idx_stride;        // 1 = int32 indices, 2 = int64 low word

// ------------------------- helpers -------------------------
__device__ __forceinline__ uint32_t smem_u32(const void* p) {
    uint32_t a;
    asm("{ .reg .u64 t; cvta.to.shared.u64 t, %1; cvt.u32.u64 %0, t; }"
        : "=r"(a) : "l"(p));
    return a;
}

// ------------------------- 0) dtype detection -------------------------
// JAX default x64-off silently makes edge_index int32; detect via odd words.
__global__ void detect_idx_kernel(const int* __restrict__ ei32, int E)
{
    __shared__ int s_nonzero;
    if (threadIdx.x == 0) s_nonzero = 0;
    __syncthreads();
    int nz = 0;
    int samples = (E < 4096) ? E : 4096;
    for (int i = threadIdx.x; i < samples; i += blockDim.x)
        nz |= ei32[2 * i + 1];
    if (nz) atomicOr(&s_nonzero, 1);
    __syncthreads();
    if (threadIdx.x == 0) g_idx_stride = s_nonzero ? 1 : 2;
}

__device__ __forceinline__ void load_edge(const int* __restrict__ ei32,
                                          int t, int E, int stride, int& s, int& d)
{
    s = ei32[(size_t)t * stride];
    d = ei32[((size_t)E + t) * stride];
}

// ------------------------- 1a) W transpose + bf16 split -------------------------
__global__ void prep_w_kernel(const float* __restrict__ W)
{
    int i = blockIdx.x * blockDim.x + threadIdx.x;   // i = k*256 + n
    if (i < DIM * DIM) {
        int k = i >> 8, n = i & 255;
        float w = W[i];
        __nv_bfloat16 hi = __float2bfloat16(w);
        __nv_bfloat16 lo = __float2bfloat16(w - __bfloat162float(hi));
        g_wthi[n * DIM + k] = hi;
        g_wtlo[n * DIM + k] = lo;
    }
}

// ------------------------- 1b) x bf16 split (+ deg zero fused) ----------
__global__ void split_x_kernel(const float* __restrict__ x, int total4, int N)
{
    int i = blockIdx.x * blockDim.x + threadIdx.x;
    if (i < total4) {
        float4 v = ((const float4*)x)[i];
        __nv_bfloat16 h0 = __float2bfloat16(v.x), h1 = __float2bfloat16(v.y);
        __nv_bfloat16 h2 = __float2bfloat16(v.z), h3 = __float2bfloat16(v.w);
        __nv_bfloat16 l0 = __float2bfloat16(v.x - __bfloat162float(h0));
        __nv_bfloat16 l1 = __float2bfloat16(v.y - __bfloat162float(h1));
        __nv_bfloat16 l2 = __float2bfloat16(v.z - __bfloat162float(h2));
        __nv_bfloat16 l3 = __float2bfloat16(v.w - __bfloat162float(h3));
        ((__nv_bfloat162*)g_xhi)[2 * i]     = __halves2bfloat162(h0, h1);
        ((__nv_bfloat162*)g_xhi)[2 * i + 1] = __halves2bfloat162(h2, h3);
        ((__nv_bfloat162*)g_xlo)[2 * i]     = __halves2bfloat162(l0, l1);
        ((__nv_bfloat162*)g_xlo)[2 * i + 1] = __halves2bfloat162(l2, l3);
    }
    if (i < N) g_deg[i] = 0;
}

// ------------------------- 2) GEMM via mma.sync bf16x3 + fused logits ---------
// h = x@W with split: hi*hi + lo*hi + hi*lo, fp32 accumulate.
// (tcgen05 is compile-blocked: harness lowers via compute_103 PTX, no 'a' feat.)
// CTA tile 64(M) x 256(N), BK=64, 8 warps (2x4), warp tile 32x64. (R11 config:
// 48KB static smem -> 2 CTAs/SM, measured 80us / L1-bound but best end-to-end.)
// Epilogue: fp16 h store + per-row att_src/att_dst dots (head == warp_n).
#define GBM 64
#define GBK 64
#define ASTR 72   // bf16 stride with +8 pad -> ldmatrix conflict-free

__global__ __launch_bounds__(256)
void gemm_mma_kernel(const float* __restrict__ att_src,
                     const float* __restrict__ att_dst, int M)
{
    __shared__ __align__(16) __nv_bfloat16 As[GBM * ASTR];   //  9216 B
    __shared__ __align__(16) __nv_bfloat16 Bs[DIM * ASTR];   // 36864 B
    __shared__ float satts[DIM], sattd[DIM];

    int tid = threadIdx.x, lane = tid & 31, wid = tid >> 5;
    int warp_m = wid & 1;        // 0..1
    int warp_n = wid >> 1;       // 0..3  (== head index)
    int brow = blockIdx.x * GBM;

    satts[tid] = att_src[tid];
    sattd[tid] = att_dst[tid];

    float acc[2][8][4];
    #pragma unroll
    for (int mi = 0; mi < 2; mi++)
        #pragma unroll
        for (int ni = 0; ni < 8; ni++)
            #pragma unroll
            for (int q = 0; q < 4; q++) acc[mi][ni][q] = 0.f;

    uint32_t As_a = smem_u32(As);
    uint32_t Bs_a = smem_u32(Bs);

    // ldmatrix lane address components
    int a_row = warp_m * 32 + (lane & 15);              // + mi*16
    int a_k   = (lane >> 4) << 3;                       // 0/8, + ks*16
    // B x4: {n+0,k0},{n+0,k8},{n+8,k0},{n+8,k8}
    int b_row = warp_n * 64 + ((lane >> 4) & 1) * 8 + (lane & 7);  // + np*16
    int b_k   = ((lane >> 3) & 1) << 3;                 // + ks*16

    for (int it = 0; it < 12; it++) {
        int pass = it >> 2, kc = it & 3;
        const __nv_bfloat16* ap = (pass == 1) ? g_xlo  : g_xhi;
        const __nv_bfloat16* bp = (pass == 2) ? g_wtlo : g_wthi;

        __syncthreads();   // previous iter's reads done
        // A: 64 rows x 64 bf16 = 512 uint4, 2 per thread
        #pragma unroll
        for (int i = 0; i < 2; i++) {
            int idx = tid + i * 256;
            int r = idx >> 3, c = (idx & 7) << 3;
            uint4 v = make_uint4(0u, 0u, 0u, 0u);
            if (brow + r < M)
                v = *(const uint4*)(ap + (size_t)(brow + r) * DIM + kc * GBK + c);
            *(uint4*)&As[r * ASTR + c] = v;
        }
        // B: 256 rows x 64 bf16 = 2048 uint4, 8 per thread
        #pragma unroll
        for (int i = 0; i < 8; i++) {
            int idx = tid + i * 256;
            int r = idx >> 3, c = (idx & 7) << 3;
            uint4 v = *(const uint4*)(bp + (size_t)r * DIM + kc * GBK + c);
            *(uint4*)&Bs[r * ASTR + c] = v;
        }
        __syncthreads();

        #pragma unroll
        for (int ks = 0; ks < 4; ks++) {
            uint32_t a_frag[2][4];
            #pragma unroll
            for (int mi = 0; mi < 2; mi++) {
                uint32_t addr = As_a +
                    (uint32_t)(((a_row + mi * 16) * ASTR + ks * 16 + a_k) * 2);
                asm volatile(
                    "ldmatrix.sync.aligned.m8n8.x4.shared.b16 {%0,%1,%2,%3}, [%4];"
                    : "=r"(a_frag[mi][0]), "=r"(a_frag[mi][1]),
                      "=r"(a_frag[mi][2]), "=r"(a_frag[mi][3])
                    : "r"(addr));
            }
            #pragma unroll
            for (int np = 0; np < 4; np++) {   // ni pairs {2np, 2np+1}
                uint32_t b0, b1, b2, b3;
                uint32_t addr = Bs_a +
                    (uint32_t)(((b_row + np * 16) * ASTR + ks * 16 + b_k) * 2);
                asm volatile(
                    "ldmatrix.sync.aligned.m8n8.x4.shared.b16 {%0,%1,%2,%3}, [%4];"
                    : "=r"(b0), "=r"(b1), "=r"(b2), "=r"(b3) : "r"(addr));
                #pragma unroll
                for (int mi = 0; mi < 2; mi++) {
                    asm volatile(
                        "mma.sync.aligned.m16n8k16.row.col.f32.bf16.bf16.f32 "
                        "{%0,%1,%2,%3}, {%4,%5,%6,%7}, {%8,%9}, {%0,%1,%2,%3};"
                        : "+f"(acc[mi][2*np][0]), "+f"(acc[mi][2*np][1]),
                          "+f"(acc[mi][2*np][2]), "+f"(acc[mi][2*np][3])
                        : "r"(a_frag[mi][0]), "r"(a_frag[mi][1]),
                          "r"(a_frag[mi][2]), "r"(a_frag[mi][3]),
                          "r"(b0), "r"(b1));
                    asm volatile(
                        "mma.sync.aligned.m16n8k16.row.col.f32.bf16.bf16.f32 "
                        "{%0,%1,%2,%3}, {%4,%5,%6,%7}, {%8,%9}, {%0,%1,%2,%3};"
                        : "+f"(acc[mi][2*np+1][0]), "+f"(acc[mi][2*np+1][1]),
                          "+f"(acc[mi][2*np+1][2]), "+f"(acc[mi][2*np+1][3])
                        : "r"(a_frag[mi][0]), "r"(a_frag[mi][1]),
                          "r"(a_frag[mi][2]), "r"(a_frag[mi][3]),
                          "r"(b2), "r"(b3));
                }
            }
        }
    }

    // Epilogue: fp16 h store + fused per-head attention dots.
    #pragma unroll
    for (int mi = 0; mi < 2; mi++) {
        int r_lo = brow + warp_m * 32 + mi * 16 + (lane >> 2);
        int r_hi = r_lo + 8;
        float s_lo = 0.f, d_lo = 0.f, s_hi = 0.f, d_hi = 0.f;
        #pragma unroll
        for (int ni = 0; ni < 8; ni++) {
            int c0 = warp_n * 64 + ni * 8 + (lane & 3) * 2;
            float v0 = acc[mi][ni][0], v1 = acc[mi][ni][1];
            float v2 = acc[mi][ni][2], v3 = acc[mi][ni][3];
            if (r_lo < M)
                *(__half2*)(g_hh + (size_t)r_lo * DIM + c0) =
                    __float22half2_rn(make_float2(v0, v1));
            if (r_hi < M)
                *(__half2*)(g_hh + (size_t)r_hi * DIM + c0) =
                    __float22half2_rn(make_float2(v2, v3));
            float ts0 = satts[c0], ts1 = satts[c0 + 1];
            float td0 = sattd[c0], td1 = sattd[c0 + 1];
            s_lo += v0 * ts0 + v1 * ts1;
            d_lo += v0 * td0 + v1 * td1;
            s_hi += v2 * ts0 + v3 * ts1;
            d_hi += v2 * td0 + v3 * td1;
        }
        #pragma unroll
        for (int off = 1; off <= 2; off <<= 1) {
            s_lo += __shfl_xor_sync(0xffffffffu, s_lo, off);
            d_lo += __shfl_xor_sync(0xffffffffu, d_lo, off);
            s_hi += __shfl_xor_sync(0xffffffffu, s_hi, off);
            d_hi += __shfl_xor_sync(0xffffffffu, d_hi, off);
        }
        if ((lane & 3) == 0) {
            if (r_lo < M) {
                ((float*)&g_asrc[r_lo])[warp_n] = s_lo;
                ((float*)&g_adst[r_lo])[warp_n] = d_lo;
            }
            if (r_hi < M) {
                ((float*)&g_asrc[r_hi])[warp_n] = s_hi;
                ((float*)&g_adst[r_hi])[warp_n] = d_hi;
            }
        }
    }
}

// ------------------------- 3) edge logits + deg count (fused) -----------------
// num = exp(leaky_relu(a_src[s] + a_dst[d])). NO denominator reduction:
// aggregate sums num itself and divides once (softmax denom cancels).
__global__ __launch_bounds__(256)
void edge_logits_kernel(const int* __restrict__ ei32, int E, int T)
{
    int t = blockIdx.x * blockDim.x + threadIdx.x;
    if (t >= T) return;
    int stride = g_idx_stride;
    int s, d;
    if (t < E) load_edge(ei32, t, E, stride, s, d);
    else       s = d = t - E;

    float4 a = g_asrc[s];
    float4 b = g_adst[d];
    float4 e = make_float4(a.x + b.x, a.y + b.y, a.z + b.z, a.w + b.w);
    e.x = e.x > 0.f ? e.x : NEG_SLOPE * e.x;
    e.y = e.y > 0.f ? e.y : NEG_SLOPE * e.y;
    e.z = e.z > 0.f ? e.z : NEG_SLOPE * e.z;
    e.w = e.w > 0.f ? e.w : NEG_SLOPE * e.w;
    // max-shift unnecessary: |e| small, exp fp32-safe, shift cancels in num/denom
    g_num[t] = make_float4(expf(e.x), expf(e.y), expf(e.z), expf(e.w));
    atomicAdd(&g_deg[d], 1);
}

// ------------------------- 4) CSR build: scan + fill -------------------------
__global__ void scan1_kernel(int N)
{
    __shared__ int sh[1024];
    int i = blockIdx.x * 1024 + threadIdx.x;
    int v = (i < N) ? g_deg[i] : 0;
    sh[threadIdx.x] = v;
    __syncthreads();
    #pragma unroll
    for (int off = 1; off < 1024; off <<= 1) {
        int t = (threadIdx.x >= off) ? sh[threadIdx.x - off] : 0;
        __syncthreads();
        sh[threadIdx.x] += t;
        __syncthreads();
    }
    if (i < N) g_rowoff[i] = sh[threadIdx.x] - v;   // exclusive within block
    if (threadIdx.x == 1023) g_bsum[blockIdx.x] = sh[1023];
}

__global__ void scan2_kernel(int nb)
{
    if (threadIdx.x == 0) {
        int run = 0;
        for (int b = 0; b < nb; b++) { g_bbase[b] = run; run += g_bsum[b]; }
    }
}

__global__ void scan3_kernel(int N)
{
    int i = blockIdx.x * blockDim.x + threadIdx.x;
    if (i < N) {
        int o = g_rowoff[i] + g_bbase[i >> 10];
        g_rowoff[i] = o;
        g_cursor[i] = o;
    }
}

__global__ void fill_kernel(const int* __restrict__ ei32, int E, int T)
{
    int t = blockIdx.x * blockDim.x + threadIdx.x;
    if (t >= T) return;
    int stride = g_idx_stride;
    int s, d;
    if (t < E) load_edge(ei32, t, E, stride, s, d);
    else       s = d = t - E;
    int pos = atomicAdd(&g_cursor[d], 1);
    g_slot[pos] = make_int2(s, t);
}

// ------------------------- 5) aggregate (warp/node) + bias + ReLU -------------
// Lane covers halves [8*lane, 8*lane+8) of the 256-wide row -> head = lane>>3.
// Softmax denom accumulated in-loop from num; single divide at the end.
__global__ __launch_bounds__(256)
void aggregate_kernel(float* __restrict__ out, const float* __restrict__ bias, int N)
{
    int g    = blockIdx.x * blockDim.x + threadIdx.x;
    int node = g >> 5;
    int lane = threadIdx.x & 31;
    if (node >= N) return;

    int off = g_rowoff[node];
    int deg = g_deg[node];
    int head = lane >> 3;

    float a0 = 0.f, a1 = 0.f, a2 = 0.f, a3 = 0.f;
    float a4 = 0.f, a5 = 0.f, a6 = 0.f, a7 = 0.f;
    float dsum = 0.f;

    const uint4* hbase = (const uint4*)g_hh;   // 32 uint4 (512B) per row
    for (int e = 0; e < deg; e++) {
        int2 sl = g_slot[off + e];
        float4 nm = g_num[sl.y];
        float w = (head == 0) ? nm.x : (head == 1) ? nm.y : (head == 2) ? nm.z : nm.w;
        dsum += w;
        uint4 v = hbase[(size_t)sl.x * 32 + lane];   // 8 halves
        float2 f0 = __half22float2(*(__half2*)&v.x);
        float2 f1 = __half22float2(*(__half2*)&v.y);
        float2 f2 = __half22float2(*(__half2*)&v.z);
        float2 f3 = __half22float2(*(__half2*)&v.w);
        a0 = fmaf(w, f0.x, a0); a1 = fmaf(w, f0.y, a1);
        a2 = fmaf(w, f1.x, a2); a3 = fmaf(w, f1.y, a3);
        a4 = fmaf(w, f2.x, a4); a5 = fmaf(w, f2.y, a5);
        a6 = fmaf(w, f3.x, a6); a7 = fmaf(w, f3.y, a7);
    }

    float inv = 1.f / dsum;   // self loops guarantee deg >= 1, dsum > 0
    const float4* b4 = (const float4*)bias;
    float4 bb0 = b4[2 * lane], bb1 = b4[2 * lane + 1];
    float4 o0 = make_float4(fmaxf(fmaf(a0, inv, bb0.x), 0.f),
                            fmaxf(fmaf(a1, inv, bb0.y), 0.f),
                            fmaxf(fmaf(a2, inv, bb0.z), 0.f),
                            fmaxf(fmaf(a3, inv, bb0.w), 0.f));
    float4 o1 = make_float4(fmaxf(fmaf(a4, inv, bb1.x), 0.f),
                            fmaxf(fmaf(a5, inv, bb1.y), 0.f),
                            fmaxf(fmaf(a6, inv, bb1.z), 0.f),
                            fmaxf(fmaf(a7, inv, bb1.w), 0.f));

    float4* orow = (float4*)(out + (size_t)node * DIM);
    orow[2 * lane]     = o0;
    orow[2 * lane + 1] = o1;
}

// ------------------------- launch -------------------------
extern "C" void kernel_launch(void* const* d_in, const int* in_sizes, int n_in,
                              void* d_out, int out_size)
{
    const float* x       = (const float*)d_in[0];
    const int*   ei32    = (const int*)d_in[1];
    const float* W       = (const float*)d_in[2];
    const float* att_src = (const float*)d_in[3];
    const float* att_dst = (const float*)d_in[4];
    const float* bias    = (const float*)d_in[5];

    int N = in_sizes[0] / DIM;   // 50000
    int E = in_sizes[1] / 2;     // 800000
    int T = E + N;
    float* out = (float*)d_out;

    // 0) edge index dtype
    detect_idx_kernel<<<1, 256>>>(ei32, E);

    // 1) bf16 splits of W^T and x (+ deg zero)
    prep_w_kernel<<<(DIM * DIM + 255) / 256, 256>>>(W);
    split_x_kernel<<<(N * DIM / 4 + 255) / 256, 256>>>(x, N * DIM / 4, N);

    // 2) tensor-core GEMM (mma.sync bf16x3) + fused attn logits + fp16 h
    gemm_mma_kernel<<<(N + GBM - 1) / GBM, 256>>>(att_src, att_dst, N);

    // 3) edge softmax numerators + degree (fused, single edge pass)
    edge_logits_kernel<<<(T + 255) / 256, 256>>>(ei32, E, T);

    // 4) CSR build
    int nb = (N + 1023) / 1024;
    scan1_kernel<<<nb, 1024>>>(N);
    scan2_kernel<<<1, 32>>>(nb);
    scan3_kernel<<<(N + 255) / 256, 256>>>(N);
    fill_kernel<<<(T + 255) / 256, 256>>>(ei32, E, T);

    // 5) per-node aggregation + bias + ReLU (denom summed in-loop)
    aggregate_kernel<<<(N * 32 + 255) / 256, 256>>>(out, bias, N);
}

// round 16
// speedup vs baseline: 1.1361x; 1.0517x over previous
#include <cuda_runtime.h>
#include <cuda_bf16.h>
#include <cuda_fp16.h>
#include <cstdint>

// N=50000 nodes, E=800000 edges, IN_DIM=256, HEADS=4, HID=64 -> out 256.
#define MAXN 50000
#define MAXE 800000
#define MAXT (MAXE + MAXN)
#define DIM 256
#define NEG_SLOPE 0.2f

// ------------------------- device scratch -------------------------
__device__ __align__(16) __half g_hh[(size_t)MAXN * DIM];  // projected features fp16
__device__ __nv_bfloat16  g_xhi[(size_t)MAXN * DIM];   // x split hi
__device__ __nv_bfloat16  g_xlo[(size_t)MAXN * DIM];   // x split lo
__device__ __nv_bfloat16  g_wthi[DIM * DIM];           // W^T split hi: [n][k]
__device__ __nv_bfloat16  g_wtlo[DIM * DIM];
__device__ float4 g_asrc[MAXN];
__device__ float4 g_adst[MAXN];
__device__ float4 g_num[MAXT];         // exp(e) per edge
__device__ int    g_deg[MAXN];
__device__ int    g_rowoff[MAXN];
__device__ int    g_cursor[MAXN];
__device__ int2   g_slot[MAXT];        // {src, edge_id} binned by dst
__device__ int    g_bsum[64];
__device__ int    g_bbase[64];
__device__ int    g_idx_stride;        // 1 = int32 indices, 2 = int64 low word

// ------------------------- helpers -------------------------
__device__ __forceinline__ uint32_t smem_u32(const void* p) {
    uint32_t a;
    asm("{ .reg .u64 t; cvta.to.shared.u64 t, %1; cvt.u32.u64 %0, t; }"
        : "=r"(a) : "l"(p));
    return a;
}

// ------------------------- 0) dtype detection -------------------------
// JAX default x64-off silently makes edge_index int32; detect via odd words.
__global__ void detect_idx_kernel(const int* __restrict__ ei32, int E)
{
    __shared__ int s_nonzero;
    if (threadIdx.x == 0) s_nonzero = 0;
    __syncthreads();
    int nz = 0;
    int samples = (E < 4096) ? E : 4096;
    for (int i = threadIdx.x; i < samples; i += blockDim.x)
        nz |= ei32[2 * i + 1];
    if (nz) atomicOr(&s_nonzero, 1);
    __syncthreads();
    if (threadIdx.x == 0) g_idx_stride = s_nonzero ? 1 : 2;
}

__device__ __forceinline__ void load_edge(const int* __restrict__ ei32,
                                          int t, int E, int stride, int& s, int& d)
{
    s = ei32[(size_t)t * stride];
    d = ei32[((size_t)E + t) * stride];
}

// ------------------------- 1a) W transpose + bf16 split -------------------------
__global__ void prep_w_kernel(const float* __restrict__ W)
{
    int i = blockIdx.x * blockDim.x + threadIdx.x;   // i = k*256 + n
    if (i < DIM * DIM) {
        int k = i >> 8, n = i & 255;
        float w = W[i];
        __nv_bfloat16 hi = __float2bfloat16(w);
        __nv_bfloat16 lo = __float2bfloat16(w - __bfloat162float(hi));
        g_wthi[n * DIM + k] = hi;
        g_wtlo[n * DIM + k] = lo;
    }
}

// ------------------------- 1b) x bf16 split (+ deg zero fused) ----------
__global__ void split_x_kernel(const float* __restrict__ x, int total4, int N)
{
    int i = blockIdx.x * blockDim.x + threadIdx.x;
    if (i < total4) {
        float4 v = ((const float4*)x)[i];
        __nv_bfloat16 h0 = __float2bfloat16(v.x), h1 = __float2bfloat16(v.y);
        __nv_bfloat16 h2 = __float2bfloat16(v.z), h3 = __float2bfloat16(v.w);
        __nv_bfloat16 l0 = __float2bfloat16(v.x - __bfloat162float(h0));
        __nv_bfloat16 l1 = __float2bfloat16(v.y - __bfloat162float(h1));
        __nv_bfloat16 l2 = __float2bfloat16(v.z - __bfloat162float(h2));
        __nv_bfloat16 l3 = __float2bfloat16(v.w - __bfloat162float(h3));
        ((__nv_bfloat162*)g_xhi)[2 * i]     = __halves2bfloat162(h0, h1);
        ((__nv_bfloat162*)g_xhi)[2 * i + 1] = __halves2bfloat162(h2, h3);
        ((__nv_bfloat162*)g_xlo)[2 * i]     = __halves2bfloat162(l0, l1);
        ((__nv_bfloat162*)g_xlo)[2 * i + 1] = __halves2bfloat162(l2, l3);
    }
    if (i < N) g_deg[i] = 0;
}

// ------------------------- 2) GEMM via mma.sync bf16x3 + fused logits ---------
// h = x@W with split: hi*hi + lo*hi + hi*lo, fp32 accumulate.
// (tcgen05 is compile-blocked: harness lowers via compute_103 PTX, no 'a' feat.)
// CTA tile 64(M) x 256(N), BK=64, 8 warps (2x4), warp tile 32x64.
// R16 restructure: kc-outer staging of all 4 tiles (Ahi,Alo,Bhi,Blo) per chunk;
// fragments shared across the 3 split passes -> LDSM/STS/LDG each cut ~33%.
// __launch_bounds__(256,2) pins regs <=128 so 2 CTAs/SM is kept (92KB dyn smem x2).
// Epilogue: fp16 h store + per-row att_src/att_dst dots (head == warp_n).
#define GBM 64
#define GBK 64
#define ASTR 72   // bf16 stride with +8 pad -> ldmatrix conflict-free
#define SM_AHI 0
#define SM_ALO (GBM * ASTR * 2)                   //  9216
#define SM_BHI (2 * GBM * ASTR * 2)               // 18432
#define SM_BLO (SM_BHI + DIM * ASTR * 2)          // 18432+36864 = 55296
#define SM_ATTS (SM_BLO + DIM * ASTR * 2)         // 92160
#define SM_ATTD (SM_ATTS + DIM * 4)
#define SMEM_GEMM (SM_ATTD + DIM * 4)             // 94208

__global__ __launch_bounds__(256, 2)
void gemm_mma_kernel(const float* __restrict__ att_src,
                     const float* __restrict__ att_dst, int M)
{
    extern __shared__ __align__(16) char dyn[];
    __nv_bfloat16* Ahi = (__nv_bfloat16*)(dyn + SM_AHI);   //  64 x 72
    __nv_bfloat16* Alo = (__nv_bfloat16*)(dyn + SM_ALO);   //  64 x 72
    __nv_bfloat16* Bhi = (__nv_bfloat16*)(dyn + SM_BHI);   // 256 x 72
    __nv_bfloat16* Blo = (__nv_bfloat16*)(dyn + SM_BLO);   // 256 x 72
    float* satts = (float*)(dyn + SM_ATTS);
    float* sattd = (float*)(dyn + SM_ATTD);

    int tid = threadIdx.x, lane = tid & 31, wid = tid >> 5;
    int warp_m = wid & 1;        // 0..1
    int warp_n = wid >> 1;       // 0..3  (== head index)
    int brow = blockIdx.x * GBM;

    satts[tid] = att_src[tid];
    sattd[tid] = att_dst[tid];

    float acc[2][8][4];
    #pragma unroll
    for (int mi = 0; mi < 2; mi++)
        #pragma unroll
        for (int ni = 0; ni < 8; ni++)
            #pragma unroll
            for (int q = 0; q < 4; q++) acc[mi][ni][q] = 0.f;

    uint32_t Ahi_a = smem_u32(Ahi);
    uint32_t Alo_a = smem_u32(Alo);
    uint32_t Bhi_a = smem_u32(Bhi);
    uint32_t Blo_a = smem_u32(Blo);

    // ldmatrix lane address components
    int a_row = warp_m * 32 + (lane & 15);              // + mi*16
    int a_k   = (lane >> 4) << 3;                       // 0/8, + ks*16
    // B x4: {n+0,k0},{n+0,k8},{n+8,k0},{n+8,k8}
    int b_row = warp_n * 64 + ((lane >> 4) & 1) * 8 + (lane & 7);  // + np*16
    int b_k   = ((lane >> 3) & 1) << 3;                 // + ks*16

    for (int kc = 0; kc < 4; kc++) {
        __syncthreads();   // previous chunk's reads done
        // A tiles: 64 rows x 64 bf16 = 512 uint4 each (hi+lo), 2 per thread each
        #pragma unroll
        for (int i = 0; i < 2; i++) {
            int idx = tid + i * 256;
            int r = idx >> 3, c = (idx & 7) << 3;
            uint4 vh = make_uint4(0u, 0u, 0u, 0u);
            uint4 vl = make_uint4(0u, 0u, 0u, 0u);
            if (brow + r < M) {
                size_t off = (size_t)(brow + r) * DIM + kc * GBK + c;
                vh = *(const uint4*)(g_xhi + off);
                vl = *(const uint4*)(g_xlo + off);
            }
            *(uint4*)&Ahi[r * ASTR + c] = vh;
            *(uint4*)&Alo[r * ASTR + c] = vl;
        }
        // B tiles: 256 rows x 64 bf16 = 2048 uint4 each (hi+lo), 8 per thread each
        #pragma unroll
        for (int i = 0; i < 8; i++) {
            int idx = tid + i * 256;
            int r = idx >> 3, c = (idx & 7) << 3;
            size_t off = (size_t)r * DIM + kc * GBK + c;
            *(uint4*)&Bhi[r * ASTR + c] = *(const uint4*)(g_wthi + off);
            *(uint4*)&Blo[r * ASTR + c] = *(const uint4*)(g_wtlo + off);
        }
        __syncthreads();

        #pragma unroll
        for (int ks = 0; ks < 4; ks++) {
            uint32_t ah[2][4], al[2][4];
            #pragma unroll
            for (int mi = 0; mi < 2; mi++) {
                uint32_t aoff =
                    (uint32_t)(((a_row + mi * 16) * ASTR + ks * 16 + a_k) * 2);
                asm volatile(
                    "ldmatrix.sync.aligned.m8n8.x4.shared.b16 {%0,%1,%2,%3}, [%4];"
                    : "=r"(ah[mi][0]), "=r"(ah[mi][1]),
                      "=r"(ah[mi][2]), "=r"(ah[mi][3])
                    : "r"(Ahi_a + aoff));
                asm volatile(
                    "ldmatrix.sync.aligned.m8n8.x4.shared.b16 {%0,%1,%2,%3}, [%4];"
                    : "=r"(al[mi][0]), "=r"(al[mi][1]),
                      "=r"(al[mi][2]), "=r"(al[mi][3])
                    : "r"(Alo_a + aoff));
            }
            #pragma unroll
            for (int np = 0; np < 4; np++) {   // ni pairs {2np, 2np+1}
                uint32_t boff =
                    (uint32_t)(((b_row + np * 16) * ASTR + ks * 16 + b_k) * 2);
                uint32_t b0, b1, b2, b3;
                // Bhi fragment: used by Ahi AND Alo passes
                asm volatile(
                    "ldmatrix.sync.aligned.m8n8.x4.shared.b16 {%0,%1,%2,%3}, [%4];"
                    : "=r"(b0), "=r"(b1), "=r"(b2), "=r"(b3) : "r"(Bhi_a + boff));
                #pragma unroll
                for (int mi = 0; mi < 2; mi++) {
                    asm volatile(
                        "mma.sync.aligned.m16n8k16.row.col.f32.bf16.bf16.f32 "
                        "{%0,%1,%2,%3}, {%4,%5,%6,%7}, {%8,%9}, {%0,%1,%2,%3};"
                        : "+f"(acc[mi][2*np][0]), "+f"(acc[mi][2*np][1]),
                          "+f"(acc[mi][2*np][2]), "+f"(acc[mi][2*np][3])
                        : "r"(ah[mi][0]), "r"(ah[mi][1]),
                          "r"(ah[mi][2]), "r"(ah[mi][3]), "r"(b0), "r"(b1));
                    asm volatile(
                        "mma.sync.aligned.m16n8k16.row.col.f32.bf16.bf16.f32 "
                        "{%0,%1,%2,%3}, {%4,%5,%6,%7}, {%8,%9}, {%0,%1,%2,%3};"
                        : "+f"(acc[mi][2*np+1][0]), "+f"(acc[mi][2*np+1][1]),
                          "+f"(acc[mi][2*np+1][2]), "+f"(acc[mi][2*np+1][3])
                        : "r"(ah[mi][0]), "r"(ah[mi][1]),
                          "r"(ah[mi][2]), "r"(ah[mi][3]), "r"(b2), "r"(b3));
                    asm volatile(
                        "mma.sync.aligned.m16n8k16.row.col.f32.bf16.bf16.f32 "
                        "{%0,%1,%2,%3}, {%4,%5,%6,%7}, {%8,%9}, {%0,%1,%2,%3};"
                        : "+f"(acc[mi][2*np][0]), "+f"(acc[mi][2*np][1]),
                          "+f"(acc[mi][2*np][2]), "+f"(acc[mi][2*np][3])
                        : "r"(al[mi][0]), "r"(al[mi][1]),
                          "r"(al[mi][2]), "r"(al[mi][3]), "r"(b0), "r"(b1));
                    asm volatile(
                        "mma.sync.aligned.m16n8k16.row.col.f32.bf16.bf16.f32 "
                        "{%0,%1,%2,%3}, {%4,%5,%6,%7}, {%8,%9}, {%0,%1,%2,%3};"
                        : "+f"(acc[mi][2*np+1][0]), "+f"(acc[mi][2*np+1][1]),
                          "+f"(acc[mi][2*np+1][2]), "+f"(acc[mi][2*np+1][3])
                        : "r"(al[mi][0]), "r"(al[mi][1]),
                          "r"(al[mi][2]), "r"(al[mi][3]), "r"(b2), "r"(b3));
                }
                // Blo fragment: used by Ahi pass only
                asm volatile(
                    "ldmatrix.sync.aligned.m8n8.x4.shared.b16 {%0,%1,%2,%3}, [%4];"
                    : "=r"(b0), "=r"(b1), "=r"(b2), "=r"(b3) : "r"(Blo_a + boff));
                #pragma unroll
                for (int mi = 0; mi < 2; mi++) {
                    asm volatile(
                        "mma.sync.aligned.m16n8k16.row.col.f32.bf16.bf16.f32 "
                        "{%0,%1,%2,%3}, {%4,%5,%6,%7}, {%8,%9}, {%0,%1,%2,%3};"
                        : "+f"(acc[mi][2*np][0]), "+f"(acc[mi][2*np][1]),
                          "+f"(acc[mi][2*np][2]), "+f"(acc[mi][2*np][3])
                        : "r"(ah[mi][0]), "r"(ah[mi][1]),
                          "r"(ah[mi][2]), "r"(ah[mi][3]), "r"(b0), "r"(b1));
                    asm volatile(
                        "mma.sync.aligned.m16n8k16.row.col.f32.bf16.bf16.f32 "
                        "{%0,%1,%2,%3}, {%4,%5,%6,%7}, {%8,%9}, {%0,%1,%2,%3};"
                        : "+f"(acc[mi][2*np+1][0]), "+f"(acc[mi][2*np+1][1]),
                          "+f"(acc[mi][2*np+1][2]), "+f"(acc[mi][2*np+1][3])
                        : "r"(ah[mi][0]), "r"(ah[mi][1]),
                          "r"(ah[mi][2]), "r"(ah[mi][3]), "r"(b2), "r"(b3));
                }
            }
        }
    }

    // Epilogue: fp16 h store + fused per-head attention dots.
    #pragma unroll
    for (int mi = 0; mi < 2; mi++) {
        int r_lo = brow + warp_m * 32 + mi * 16 + (lane >> 2);
        int r_hi = r_lo + 8;
        float s_lo = 0.f, d_lo = 0.f, s_hi = 0.f, d_hi = 0.f;
        #pragma unroll
        for (int ni = 0; ni < 8; ni++) {
            int c0 = warp_n * 64 + ni * 8 + (lane & 3) * 2;
            float v0 = acc[mi][ni][0], v1 = acc[mi][ni][1];
            float v2 = acc[mi][ni][2], v3 = acc[mi][ni][3];
            if (r_lo < M)
                *(__half2*)(g_hh + (size_t)r_lo * DIM + c0) =
                    __float22half2_rn(make_float2(v0, v1));
            if (r_hi < M)
                *(__half2*)(g_hh + (size_t)r_hi * DIM + c0) =
                    __float22half2_rn(make_float2(v2, v3));
            float ts0 = satts[c0], ts1 = satts[c0 + 1];
            float td0 = sattd[c0], td1 = sattd[c0 + 1];
            s_lo += v0 * ts0 + v1 * ts1;
            d_lo += v0 * td0 + v1 * td1;
            s_hi += v2 * ts0 + v3 * ts1;
            d_hi += v2 * td0 + v3 * td1;
        }
        #pragma unroll
        for (int off = 1; off <= 2; off <<= 1) {
            s_lo += __shfl_xor_sync(0xffffffffu, s_lo, off);
            d_lo += __shfl_xor_sync(0xffffffffu, d_lo, off);
            s_hi += __shfl_xor_sync(0xffffffffu, s_hi, off);
            d_hi += __shfl_xor_sync(0xffffffffu, d_hi, off);
        }
        if ((lane & 3) == 0) {
            if (r_lo < M) {
                ((float*)&g_asrc[r_lo])[warp_n] = s_lo;
                ((float*)&g_adst[r_lo])[warp_n] = d_lo;
            }
            if (r_hi < M) {
                ((float*)&g_asrc[r_hi])[warp_n] = s_hi;
                ((float*)&g_adst[r_hi])[warp_n] = d_hi;
            }
        }
    }
}

// ------------------------- 3) edge logits + deg count (fused) -----------------
// num = exp(leaky_relu(a_src[s] + a_dst[d])). NO denominator reduction:
// aggregate sums num itself and divides once (softmax denom cancels).
__global__ __launch_bounds__(256)
void edge_logits_kernel(const int* __restrict__ ei32, int E, int T)
{
    int t = blockIdx.x * blockDim.x + threadIdx.x;
    if (t >= T) return;
    int stride = g_idx_stride;
    int s, d;
    if (t < E) load_edge(ei32, t, E, stride, s, d);
    else       s = d = t - E;

    float4 a = g_asrc[s];
    float4 b = g_adst[d];
    float4 e = make_float4(a.x + b.x, a.y + b.y, a.z + b.z, a.w + b.w);
    e.x = e.x > 0.f ? e.x : NEG_SLOPE * e.x;
    e.y = e.y > 0.f ? e.y : NEG_SLOPE * e.y;
    e.z = e.z > 0.f ? e.z : NEG_SLOPE * e.z;
    e.w = e.w > 0.f ? e.w : NEG_SLOPE * e.w;
    // max-shift unnecessary: |e| small, exp fp32-safe, shift cancels in num/denom
    g_num[t] = make_float4(expf(e.x), expf(e.y), expf(e.z), expf(e.w));
    atomicAdd(&g_deg[d], 1);
}

// ------------------------- 4) CSR build: scan + fill -------------------------
__global__ void scan1_kernel(int N)
{
    __shared__ int sh[1024];
    int i = blockIdx.x * 1024 + threadIdx.x;
    int v = (i < N) ? g_deg[i] : 0;
    sh[threadIdx.x] = v;
    __syncthreads();
    #pragma unroll
    for (int off = 1; off < 1024; off <<= 1) {
        int t = (threadIdx.x >= off) ? sh[threadIdx.x - off] : 0;
        __syncthreads();
        sh[threadIdx.x] += t;
        __syncthreads();
    }
    if (i < N) g_rowoff[i] = sh[threadIdx.x] - v;   // exclusive within block
    if (threadIdx.x == 1023) g_bsum[blockIdx.x] = sh[1023];
}

__global__ void scan2_kernel(int nb)
{
    if (threadIdx.x == 0) {
        int run = 0;
        for (int b = 0; b < nb; b++) { g_bbase[b] = run; run += g_bsum[b]; }
    }
}

__global__ void scan3_kernel(int N)
{
    int i = blockIdx.x * blockDim.x + threadIdx.x;
    if (i < N) {
        int o = g_rowoff[i] + g_bbase[i >> 10];
        g_rowoff[i] = o;
        g_cursor[i] = o;
    }
}

__global__ void fill_kernel(const int* __restrict__ ei32, int E, int T)
{
    int t = blockIdx.x * blockDim.x + threadIdx.x;
    if (t >= T) return;
    int stride = g_idx_stride;
    int s, d;
    if (t < E) load_edge(ei32, t, E, stride, s, d);
    else       s = d = t - E;
    int pos = atomicAdd(&g_cursor[d], 1);
    g_slot[pos] = make_int2(s, t);
}

// ------------------------- 5) aggregate (warp/node) + bias + ReLU -------------
// Lane covers halves [8*lane, 8*lane+8) of the 256-wide row -> head = lane>>3.
// Softmax denom accumulated in-loop from num; single divide at the end.
__global__ __launch_bounds__(256)
void aggregate_kernel(float* __restrict__ out, const float* __restrict__ bias, int N)
{
    int g    = blockIdx.x * blockDim.x + threadIdx.x;
    int node = g >> 5;
    int lane = threadIdx.x & 31;
    if (node >= N) return;

    int off = g_rowoff[node];
    int deg = g_deg[node];
    int head = lane >> 3;

    float a0 = 0.f, a1 = 0.f, a2 = 0.f, a3 = 0.f;
    float a4 = 0.f, a5 = 0.f, a6 = 0.f, a7 = 0.f;
    float dsum = 0.f;

    const uint4* hbase = (const uint4*)g_hh;   // 32 uint4 (512B) per row
    for (int e = 0; e < deg; e++) {
        int2 sl = g_slot[off + e];
        float4 nm = g_num[sl.y];
        float w = (head == 0) ? nm.x : (head == 1) ? nm.y : (head == 2) ? nm.z : nm.w;
        dsum += w;
        uint4 v = hbase[(size_t)sl.x * 32 + lane];   // 8 halves
        float2 f0 = __half22float2(*(__half2*)&v.x);
        float2 f1 = __half22float2(*(__half2*)&v.y);
        float2 f2 = __half22float2(*(__half2*)&v.z);
        float2 f3 = __half22float2(*(__half2*)&v.w);
        a0 = fmaf(w, f0.x, a0); a1 = fmaf(w, f0.y, a1);
        a2 = fmaf(w, f1.x, a2); a3 = fmaf(w, f1.y, a3);
        a4 = fmaf(w, f2.x, a4); a5 = fmaf(w, f2.y, a5);
        a6 = fmaf(w, f3.x, a6); a7 = fmaf(w, f3.y, a7);
    }

    float inv = 1.f / dsum;   // self loops guarantee deg >= 1, dsum > 0
    const float4* b4 = (const float4*)bias;
    float4 bb0 = b4[2 * lane], bb1 = b4[2 * lane + 1];
    float4 o0 = make_float4(fmaxf(fmaf(a0, inv, bb0.x), 0.f),
                            fmaxf(fmaf(a1, inv, bb0.y), 0.f),
                            fmaxf(fmaf(a2, inv, bb0.z), 0.f),
                            fmaxf(fmaf(a3, inv, bb0.w), 0.f));
    float4 o1 = make_float4(fmaxf(fmaf(a4, inv, bb1.x), 0.f),
                            fmaxf(fmaf(a5, inv, bb1.y), 0.f),
                            fmaxf(fmaf(a6, inv, bb1.z), 0.f),
                            fmaxf(fmaf(a7, inv, bb1.w), 0.f));

    float4* orow = (float4*)(out + (size_t)node * DIM);
    orow[2 * lane]     = o0;
    orow[2 * lane + 1] = o1;
}

// ------------------------- launch -------------------------
extern "C" void kernel_launch(void* const* d_in, const int* in_sizes, int n_in,
                              void* d_out, int out_size)
{
    const float* x       = (const float*)d_in[0];
    const int*   ei32    = (const int*)d_in[1];
    const float* W       = (const float*)d_in[2];
    const float* att_src = (const float*)d_in[3];
    const float* att_dst = (const float*)d_in[4];
    const float* bias    = (const float*)d_in[5];

    int N = in_sizes[0] / DIM;   // 50000
    int E = in_sizes[1] / 2;     // 800000
    int T = E + N;
    float* out = (float*)d_out;

    static int s_attr_done = 0;
    if (!s_attr_done) {
        cudaFuncSetAttribute(gemm_mma_kernel,
                             cudaFuncAttributeMaxDynamicSharedMemorySize, SMEM_GEMM);
        s_attr_done = 1;
    }

    // 0) edge index dtype
    detect_idx_kernel<<<1, 256>>>(ei32, E);

    // 1) bf16 splits of W^T and x (+ deg zero)
    prep_w_kernel<<<(DIM * DIM + 255) / 256, 256>>>(W);
    split_x_kernel<<<(N * DIM / 4 + 255) / 256, 256>>>(x, N * DIM / 4, N);

    // 2) tensor-core GEMM (mma.sync bf16x3, 4-tile kc staging) + fused logits
    gemm_mma_kernel<<<(N + GBM - 1) / GBM, 256, SMEM_GEMM>>>(att_src, att_dst, N);

    // 3) edge softmax numerators + degree (fused, single edge pass)
    edge_logits_kernel<<<(T + 255) / 256, 256>>>(ei32, E, T);

    // 4) CSR build
    int nb = (N + 1023) / 1024;
    scan1_kernel<<<nb, 1024>>>(N);
    scan2_kernel<<<1, 32>>>(nb);
    scan3_kernel<<<(N + 255) / 256, 256>>>(N);
    fill_kernel<<<(T + 255) / 256, 256>>>(ei32, E, T);

    // 5) per-node aggregation + bias + ReLU (denom summed in-loop)
    aggregate_kernel<<<(N * 32 + 255) / 256, 256>>>(out, bias, N);
}

// round 17
// speedup vs baseline: 1.2363x; 1.0882x over previous
#include <cuda_runtime.h>
#include <cuda_bf16.h>
#include <cuda_fp16.h>
#include <cstdint>

// N=50000 nodes, E=800000 edges, IN_DIM=256, HEADS=4, HID=64 -> out 256.
#define MAXN 50000
#define MAXE 800000
#define MAXT (MAXE + MAXN)
#define DIM 256
#define NEG_SLOPE 0.2f

// ------------------------- device scratch -------------------------
__device__ __align__(16) __half g_hh[(size_t)MAXN * DIM];  // projected features fp16
__device__ __nv_bfloat16  g_wthi[DIM * DIM];           // W^T split hi: [n][k]
__device__ __nv_bfloat16  g_wtlo[DIM * DIM];
__device__ float4 g_asrc[MAXN];
__device__ float4 g_adst[MAXN];
__device__ float4 g_num[MAXT];         // exp(e) per edge
__device__ int    g_deg[MAXN];
__device__ int    g_rowoff[MAXN];
__device__ int    g_cursor[MAXN];
__device__ int2   g_slot[MAXT];        // {src, edge_id} binned by dst
__device__ int    g_bsum[64];
__device__ int    g_bbase[64];
__device__ int    g_idx_stride;        // 1 = int32 indices, 2 = int64 low word

// ------------------------- helpers -------------------------
__device__ __forceinline__ uint32_t smem_u32(const void* p) {
    uint32_t a;
    asm("{ .reg .u64 t; cvta.to.shared.u64 t, %1; cvt.u32.u64 %0, t; }"
        : "=r"(a) : "l"(p));
    return a;
}

// ------------------------- 0) dtype detection -------------------------
// JAX default x64-off silently makes edge_index int32; detect via odd words.
__global__ void detect_idx_kernel(const int* __restrict__ ei32, int E)
{
    __shared__ int s_nonzero;
    if (threadIdx.x == 0) s_nonzero = 0;
    __syncthreads();
    int nz = 0;
    int samples = (E < 4096) ? E : 4096;
    for (int i = threadIdx.x; i < samples; i += blockDim.x)
        nz |= ei32[2 * i + 1];
    if (nz) atomicOr(&s_nonzero, 1);
    __syncthreads();
    if (threadIdx.x == 0) g_idx_stride = s_nonzero ? 1 : 2;
}

__device__ __forceinline__ void load_edge(const int* __restrict__ ei32,
                                          int t, int E, int stride, int& s, int& d)
{
    s = ei32[(size_t)t * stride];
    d = ei32[((size_t)E + t) * stride];
}

// ------------------------- 1) W transpose + bf16 split (+ deg zero) -----------
__global__ void prep_w_kernel(const float* __restrict__ W, int N)
{
    int i = blockIdx.x * blockDim.x + threadIdx.x;   // i = k*256 + n
    if (i < DIM * DIM) {
        int k = i >> 8, n = i & 255;
        float w = W[i];
        __nv_bfloat16 hi = __float2bfloat16(w);
        __nv_bfloat16 lo = __float2bfloat16(w - __bfloat162float(hi));
        g_wthi[n * DIM + k] = hi;
        g_wtlo[n * DIM + k] = lo;
    }
    if (i < N) g_deg[i] = 0;
}

// ------------------------- 2) GEMM via mma.sync bf16x3 + fused logits ---------
// h = x@W with split: hi*hi + lo*hi + hi*lo, fp32 accumulate.
// (tcgen05 is compile-blocked: harness lowers via compute_103 PTX, no 'a' feat.)
// CTA tile 64(M) x 256(N), BK=64, 8 warps (2x4), warp tile 32x64.
// kc-outer staging of all 4 tiles; fragments shared across the 3 split passes.
// R17: A hi/lo split computed in-register during staging from fp32 x directly
// (kills the standalone split_x kernel and its 102MB round-trip).
// Epilogue: fp16 h store + per-row att_src/att_dst dots (head == warp_n).
#define GBM 64
#define GBK 64
#define ASTR 72   // bf16 stride with +8 pad -> ldmatrix conflict-free
#define SM_AHI 0
#define SM_ALO (GBM * ASTR * 2)                   //  9216
#define SM_BHI (2 * GBM * ASTR * 2)               // 18432
#define SM_BLO (SM_BHI + DIM * ASTR * 2)          // 18432+36864 = 55296
#define SM_ATTS (SM_BLO + DIM * ASTR * 2)         // 92160
#define SM_ATTD (SM_ATTS + DIM * 4)
#define SMEM_GEMM (SM_ATTD + DIM * 4)             // 94208

__global__ __launch_bounds__(256, 2)
void gemm_mma_kernel(const float* __restrict__ x,
                     const float* __restrict__ att_src,
                     const float* __restrict__ att_dst, int M)
{
    extern __shared__ __align__(16) char dyn[];
    __nv_bfloat16* Ahi = (__nv_bfloat16*)(dyn + SM_AHI);   //  64 x 72
    __nv_bfloat16* Alo = (__nv_bfloat16*)(dyn + SM_ALO);   //  64 x 72
    __nv_bfloat16* Bhi = (__nv_bfloat16*)(dyn + SM_BHI);   // 256 x 72
    __nv_bfloat16* Blo = (__nv_bfloat16*)(dyn + SM_BLO);   // 256 x 72
    float* satts = (float*)(dyn + SM_ATTS);
    float* sattd = (float*)(dyn + SM_ATTD);

    int tid = threadIdx.x, lane = tid & 31, wid = tid >> 5;
    int warp_m = wid & 1;        // 0..1
    int warp_n = wid >> 1;       // 0..3  (== head index)
    int brow = blockIdx.x * GBM;

    satts[tid] = att_src[tid];
    sattd[tid] = att_dst[tid];

    float acc[2][8][4];
    #pragma unroll
    for (int mi = 0; mi < 2; mi++)
        #pragma unroll
        for (int ni = 0; ni < 8; ni++)
            #pragma unroll
            for (int q = 0; q < 4; q++) acc[mi][ni][q] = 0.f;

    uint32_t Ahi_a = smem_u32(Ahi);
    uint32_t Alo_a = smem_u32(Alo);
    uint32_t Bhi_a = smem_u32(Bhi);
    uint32_t Blo_a = smem_u32(Blo);

    // ldmatrix lane address components
    int a_row = warp_m * 32 + (lane & 15);              // + mi*16
    int a_k   = (lane >> 4) << 3;                       // 0/8, + ks*16
    // B x4: {n+0,k0},{n+0,k8},{n+8,k0},{n+8,k8}
    int b_row = warp_n * 64 + ((lane >> 4) & 1) * 8 + (lane & 7);  // + np*16
    int b_k   = ((lane >> 3) & 1) << 3;                 // + ks*16

    for (int kc = 0; kc < 4; kc++) {
        __syncthreads();   // previous chunk's reads done
        // A tile: 64 rows x 64 cols; load fp32 x, split to bf16 hi/lo in-register
        #pragma unroll
        for (int i = 0; i < 2; i++) {
            int idx = tid + i * 256;
            int r = idx >> 3, c = (idx & 7) << 3;   // 8 cols per thread
            union { uint4 u; __nv_bfloat162 b[4]; } ph, pl;
            ph.u = make_uint4(0u, 0u, 0u, 0u);
            pl.u = make_uint4(0u, 0u, 0u, 0u);
            if (brow + r < M) {
                const float* xp = x + (size_t)(brow + r) * DIM + kc * GBK + c;
                float4 f0 = *(const float4*)xp;
                float4 f1 = *(const float4*)(xp + 4);
                float fs[8] = {f0.x, f0.y, f0.z, f0.w, f1.x, f1.y, f1.z, f1.w};
                __nv_bfloat16 h[8], l[8];
                #pragma unroll
                for (int q = 0; q < 8; q++) {
                    h[q] = __float2bfloat16(fs[q]);
                    l[q] = __float2bfloat16(fs[q] - __bfloat162float(h[q]));
                }
                #pragma unroll
                for (int q = 0; q < 4; q++) {
                    ph.b[q] = __halves2bfloat162(h[2*q], h[2*q+1]);
                    pl.b[q] = __halves2bfloat162(l[2*q], l[2*q+1]);
                }
            }
            *(uint4*)&Ahi[r * ASTR + c] = ph.u;
            *(uint4*)&Alo[r * ASTR + c] = pl.u;
        }
        // B tiles: 256 rows x 64 bf16 = 2048 uint4 each (hi+lo), 8 per thread each
        #pragma unroll
        for (int i = 0; i < 8; i++) {
            int idx = tid + i * 256;
            int r = idx >> 3, c = (idx & 7) << 3;
            size_t off = (size_t)r * DIM + kc * GBK + c;
            *(uint4*)&Bhi[r * ASTR + c] = *(const uint4*)(g_wthi + off);
            *(uint4*)&Blo[r * ASTR + c] = *(const uint4*)(g_wtlo + off);
        }
        __syncthreads();

        #pragma unroll
        for (int ks = 0; ks < 4; ks++) {
            uint32_t ah[2][4], al[2][4];
            #pragma unroll
            for (int mi = 0; mi < 2; mi++) {
                uint32_t aoff =
                    (uint32_t)(((a_row + mi * 16) * ASTR + ks * 16 + a_k) * 2);
                asm volatile(
                    "ldmatrix.sync.aligned.m8n8.x4.shared.b16 {%0,%1,%2,%3}, [%4];"
                    : "=r"(ah[mi][0]), "=r"(ah[mi][1]),
                      "=r"(ah[mi][2]), "=r"(ah[mi][3])
                    : "r"(Ahi_a + aoff));
                asm volatile(
                    "ldmatrix.sync.aligned.m8n8.x4.shared.b16 {%0,%1,%2,%3}, [%4];"
                    : "=r"(al[mi][0]), "=r"(al[mi][1]),
                      "=r"(al[mi][2]), "=r"(al[mi][3])
                    : "r"(Alo_a + aoff));
            }
            #pragma unroll
            for (int np = 0; np < 4; np++) {   // ni pairs {2np, 2np+1}
                uint32_t boff =
                    (uint32_t)(((b_row + np * 16) * ASTR + ks * 16 + b_k) * 2);
                uint32_t b0, b1, b2, b3;
                // Bhi fragment: used by Ahi AND Alo passes
                asm volatile(
                    "ldmatrix.sync.aligned.m8n8.x4.shared.b16 {%0,%1,%2,%3}, [%4];"
                    : "=r"(b0), "=r"(b1), "=r"(b2), "=r"(b3) : "r"(Bhi_a + boff));
                #pragma unroll
                for (int mi = 0; mi < 2; mi++) {
                    asm volatile(
                        "mma.sync.aligned.m16n8k16.row.col.f32.bf16.bf16.f32 "
                        "{%0,%1,%2,%3}, {%4,%5,%6,%7}, {%8,%9}, {%0,%1,%2,%3};"
                        : "+f"(acc[mi][2*np][0]), "+f"(acc[mi][2*np][1]),
                          "+f"(acc[mi][2*np][2]), "+f"(acc[mi][2*np][3])
                        : "r"(ah[mi][0]), "r"(ah[mi][1]),
                          "r"(ah[mi][2]), "r"(ah[mi][3]), "r"(b0), "r"(b1));
                    asm volatile(
                        "mma.sync.aligned.m16n8k16.row.col.f32.bf16.bf16.f32 "
                        "{%0,%1,%2,%3}, {%4,%5,%6,%7}, {%8,%9}, {%0,%1,%2,%3};"
                        : "+f"(acc[mi][2*np+1][0]), "+f"(acc[mi][2*np+1][1]),
                          "+f"(acc[mi][2*np+1][2]), "+f"(acc[mi][2*np+1][3])
                        : "r"(ah[mi][0]), "r"(ah[mi][1]),
                          "r"(ah[mi][2]), "r"(ah[mi][3]), "r"(b2), "r"(b3));
                    asm volatile(
                        "mma.sync.aligned.m16n8k16.row.col.f32.bf16.bf16.f32 "
                        "{%0,%1,%2,%3}, {%4,%5,%6,%7}, {%8,%9}, {%0,%1,%2,%3};"
                        : "+f"(acc[mi][2*np][0]), "+f"(acc[mi][2*np][1]),
                          "+f"(acc[mi][2*np][2]), "+f"(acc[mi][2*np][3])
                        : "r"(al[mi][0]), "r"(al[mi][1]),
                          "r"(al[mi][2]), "r"(al[mi][3]), "r"(b0), "r"(b1));
                    asm volatile(
                        "mma.sync.aligned.m16n8k16.row.col.f32.bf16.bf16.f32 "
                        "{%0,%1,%2,%3}, {%4,%5,%6,%7}, {%8,%9}, {%0,%1,%2,%3};"
                        : "+f"(acc[mi][2*np+1][0]), "+f"(acc[mi][2*np+1][1]),
                          "+f"(acc[mi][2*np+1][2]), "+f"(acc[mi][2*np+1][3])
                        : "r"(al[mi][0]), "r"(al[mi][1]),
                          "r"(al[mi][2]), "r"(al[mi][3]), "r"(b2), "r"(b3));
                }
                // Blo fragment: used by Ahi pass only
                asm volatile(
                    "ldmatrix.sync.aligned.m8n8.x4.shared.b16 {%0,%1,%2,%3}, [%4];"
                    : "=r"(b0), "=r"(b1), "=r"(b2), "=r"(b3) : "r"(Blo_a + boff));
                #pragma unroll
                for (int mi = 0; mi < 2; mi++) {
                    asm volatile(
                        "mma.sync.aligned.m16n8k16.row.col.f32.bf16.bf16.f32 "
                        "{%0,%1,%2,%3}, {%4,%5,%6,%7}, {%8,%9}, {%0,%1,%2,%3};"
                        : "+f"(acc[mi][2*np][0]), "+f"(acc[mi][2*np][1]),
                          "+f"(acc[mi][2*np][2]), "+f"(acc[mi][2*np][3])
                        : "r"(ah[mi][0]), "r"(ah[mi][1]),
                          "r"(ah[mi][2]), "r"(ah[mi][3]), "r"(b0), "r"(b1));
                    asm volatile(
                        "mma.sync.aligned.m16n8k16.row.col.f32.bf16.bf16.f32 "
                        "{%0,%1,%2,%3}, {%4,%5,%6,%7}, {%8,%9}, {%0,%1,%2,%3};"
                        : "+f"(acc[mi][2*np+1][0]), "+f"(acc[mi][2*np+1][1]),
                          "+f"(acc[mi][2*np+1][2]), "+f"(acc[mi][2*np+1][3])
                        : "r"(ah[mi][0]), "r"(ah[mi][1]),
                          "r"(ah[mi][2]), "r"(ah[mi][3]), "r"(b2), "r"(b3));
                }
            }
        }
    }

    // Epilogue: fp16 h store + fused per-head attention dots.
    #pragma unroll
    for (int mi = 0; mi < 2; mi++) {
        int r_lo = brow + warp_m * 32 + mi * 16 + (lane >> 2);
        int r_hi = r_lo + 8;
        float s_lo = 0.f, d_lo = 0.f, s_hi = 0.f, d_hi = 0.f;
        #pragma unroll
        for (int ni = 0; ni < 8; ni++) {
            int c0 = warp_n * 64 + ni * 8 + (lane & 3) * 2;
            float v0 = acc[mi][ni][0], v1 = acc[mi][ni][1];
            float v2 = acc[mi][ni][2], v3 = acc[mi][ni][3];
            if (r_lo < M)
                *(__half2*)(g_hh + (size_t)r_lo * DIM + c0) =
                    __float22half2_rn(make_float2(v0, v1));
            if (r_hi < M)
                *(__half2*)(g_hh + (size_t)r_hi * DIM + c0) =
                    __float22half2_rn(make_float2(v2, v3));
            float ts0 = satts[c0], ts1 = satts[c0 + 1];
            float td0 = sattd[c0], td1 = sattd[c0 + 1];
            s_lo += v0 * ts0 + v1 * ts1;
            d_lo += v0 * td0 + v1 * td1;
            s_hi += v2 * ts0 + v3 * ts1;
            d_hi += v2 * td0 + v3 * td1;
        }
        #pragma unroll
        for (int off = 1; off <= 2; off <<= 1) {
            s_lo += __shfl_xor_sync(0xffffffffu, s_lo, off);
            d_lo += __shfl_xor_sync(0xffffffffu, d_lo, off);
            s_hi += __shfl_xor_sync(0xffffffffu, s_hi, off);
            d_hi += __shfl_xor_sync(0xffffffffu, d_hi, off);
        }
        if ((lane & 3) == 0) {
            if (r_lo < M) {
                ((float*)&g_asrc[r_lo])[warp_n] = s_lo;
                ((float*)&g_adst[r_lo])[warp_n] = d_lo;
            }
            if (r_hi < M) {
                ((float*)&g_asrc[r_hi])[warp_n] = s_hi;
                ((float*)&g_adst[r_hi])[warp_n] = d_hi;
            }
        }
    }
}

// ------------------------- 3) edge logits + deg count (fused) -----------------
// num = exp(leaky_relu(a_src[s] + a_dst[d])). NO denominator reduction:
// aggregate sums num itself and divides once (softmax denom cancels).
__global__ __launch_bounds__(256)
void edge_logits_kernel(const int* __restrict__ ei32, int E, int T)
{
    int t = blockIdx.x * blockDim.x + threadIdx.x;
    if (t >= T) return;
    int stride = g_idx_stride;
    int s, d;
    if (t < E) load_edge(ei32, t, E, stride, s, d);
    else       s = d = t - E;

    float4 a = g_asrc[s];
    float4 b = g_adst[d];
    float4 e = make_float4(a.x + b.x, a.y + b.y, a.z + b.z, a.w + b.w);
    e.x = e.x > 0.f ? e.x : NEG_SLOPE * e.x;
    e.y = e.y > 0.f ? e.y : NEG_SLOPE * e.y;
    e.z = e.z > 0.f ? e.z : NEG_SLOPE * e.z;
    e.w = e.w > 0.f ? e.w : NEG_SLOPE * e.w;
    // max-shift unnecessary: |e| small, exp fp32-safe, shift cancels in num/denom
    g_num[t] = make_float4(expf(e.x), expf(e.y), expf(e.z), expf(e.w));
    atomicAdd(&g_deg[d], 1);
}

// ------------------------- 4) CSR build: scan + fill -------------------------
__global__ void scan1_kernel(int N)
{
    __shared__ int sh[1024];
    int i = blockIdx.x * 1024 + threadIdx.x;
    int v = (i < N) ? g_deg[i] : 0;
    sh[threadIdx.x] = v;
    __syncthreads();
    #pragma unroll
    for (int off = 1; off < 1024; off <<= 1) {
        int t = (threadIdx.x >= off) ? sh[threadIdx.x - off] : 0;
        __syncthreads();
        sh[threadIdx.x] += t;
        __syncthreads();
    }
    if (i < N) g_rowoff[i] = sh[threadIdx.x] - v;   // exclusive within block
    if (threadIdx.x == 1023) g_bsum[blockIdx.x] = sh[1023];
}

__global__ void scan2_kernel(int nb)
{
    if (threadIdx.x == 0) {
        int run = 0;
        for (int b = 0; b < nb; b++) { g_bbase[b] = run; run += g_bsum[b]; }
    }
}

__global__ void scan3_kernel(int N)
{
    int i = blockIdx.x * blockDim.x + threadIdx.x;
    if (i < N) {
        int o = g_rowoff[i] + g_bbase[i >> 10];
        g_rowoff[i] = o;
        g_cursor[i] = o;
    }
}

__global__ void fill_kernel(const int* __restrict__ ei32, int E, int T)
{
    int t = blockIdx.x * blockDim.x + threadIdx.x;
    if (t >= T) return;
    int stride = g_idx_stride;
    int s, d;
    if (t < E) load_edge(ei32, t, E, stride, s, d);
    else       s = d = t - E;
    int pos = atomicAdd(&g_cursor[d], 1);
    g_slot[pos] = make_int2(s, t);
}

// ------------------------- 5) aggregate (warp/node) + bias + ReLU -------------
// Lane covers halves [8*lane, 8*lane+8) of the 256-wide row -> head = lane>>3.
// Softmax denom accumulated in-loop from num; single divide at the end.
__global__ __launch_bounds__(256)
void aggregate_kernel(float* __restrict__ out, const float* __restrict__ bias, int N)
{
    int g    = blockIdx.x * blockDim.x + threadIdx.x;
    int node = g >> 5;
    int lane = threadIdx.x & 31;
    if (node >= N) return;

    int off = g_rowoff[node];
    int deg = g_deg[node];
    int head = lane >> 3;

    float a0 = 0.f, a1 = 0.f, a2 = 0.f, a3 = 0.f;
    float a4 = 0.f, a5 = 0.f, a6 = 0.f, a7 = 0.f;
    float dsum = 0.f;

    const uint4* hbase = (const uint4*)g_hh;   // 32 uint4 (512B) per row
    for (int e = 0; e < deg; e++) {
        int2 sl = g_slot[off + e];
        float4 nm = g_num[sl.y];
        float w = (head == 0) ? nm.x : (head == 1) ? nm.y : (head == 2) ? nm.z : nm.w;
        dsum += w;
        uint4 v = hbase[(size_t)sl.x * 32 + lane];   // 8 halves
        float2 f0 = __half22float2(*(__half2*)&v.x);
        float2 f1 = __half22float2(*(__half2*)&v.y);
        float2 f2 = __half22float2(*(__half2*)&v.z);
        float2 f3 = __half22float2(*(__half2*)&v.w);
        a0 = fmaf(w, f0.x, a0); a1 = fmaf(w, f0.y, a1);
        a2 = fmaf(w, f1.x, a2); a3 = fmaf(w, f1.y, a3);
        a4 = fmaf(w, f2.x, a4); a5 = fmaf(w, f2.y, a5);
        a6 = fmaf(w, f3.x, a6); a7 = fmaf(w, f3.y, a7);
    }

    float inv = 1.f / dsum;   // self loops guarantee deg >= 1, dsum > 0
    const float4* b4 = (const float4*)bias;
    float4 bb0 = b4[2 * lane], bb1 = b4[2 * lane + 1];
    float4 o0 = make_float4(fmaxf(fmaf(a0, inv, bb0.x), 0.f),
                            fmaxf(fmaf(a1, inv, bb0.y), 0.f),
                            fmaxf(fmaf(a2, inv, bb0.z), 0.f),
                            fmaxf(fmaf(a3, inv, bb0.w), 0.f));
    float4 o1 = make_float4(fmaxf(fmaf(a4, inv, bb1.x), 0.f),
                            fmaxf(fmaf(a5, inv, bb1.y), 0.f),
                            fmaxf(fmaf(a6, inv, bb1.z), 0.f),
                            fmaxf(fmaf(a7, inv, bb1.w), 0.f));

    float4* orow = (float4*)(out + (size_t)node * DIM);
    orow[2 * lane]     = o0;
    orow[2 * lane + 1] = o1;
}

// ------------------------- launch -------------------------
extern "C" void kernel_launch(void* const* d_in, const int* in_sizes, int n_in,
                              void* d_out, int out_size)
{
    const float* x       = (const float*)d_in[0];
    const int*   ei32    = (const int*)d_in[1];
    const float* W       = (const float*)d_in[2];
    const float* att_src = (const float*)d_in[3];
    const float* att_dst = (const float*)d_in[4];
    const float* bias    = (const float*)d_in[5];

    int N = in_sizes[0] / DIM;   // 50000
    int E = in_sizes[1] / 2;     // 800000
    int T = E + N;
    float* out = (float*)d_out;

    static int s_attr_done = 0;
    if (!s_attr_done) {
        cudaFuncSetAttribute(gemm_mma_kernel,
                             cudaFuncAttributeMaxDynamicSharedMemorySize, SMEM_GEMM);
        s_attr_done = 1;
    }

    // 0) edge index dtype
    detect_idx_kernel<<<1, 256>>>(ei32, E);

    // 1) bf16 split of W^T (+ deg zero; grid covers max(DIM*DIM, N))
    int prep_n = DIM * DIM > N ? DIM * DIM : N;
    prep_w_kernel<<<(prep_n + 255) / 256, 256>>>(W, N);

    // 2) tensor-core GEMM (mma.sync bf16x3, in-register x split) + fused logits
    gemm_mma_kernel<<<(N + GBM - 1) / GBM, 256, SMEM_GEMM>>>(x, att_src, att_dst, N);

    // 3) edge softmax numerators + degree (fused, single edge pass)
    edge_logits_kernel<<<(T + 255) / 256, 256>>>(ei32, E, T);

    // 4) CSR build
    int nb = (N + 1023) / 1024;
    scan1_kernel<<<nb, 1024>>>(N);
    scan2_kernel<<<1, 32>>>(nb);
    scan3_kernel<<<(N + 255) / 256, 256>>>(N);
    fill_kernel<<<(T + 255) / 256, 256>>>(ei32, E, T);

    // 5) per-node aggregation + bias + ReLU (denom summed in-loop)
    aggregate_kernel<<<(N * 32 + 255) / 256, 256>>>(out, bias, N);
}